// round 10
// baseline (speedup 1.0000x reference)
#include <cuda_runtime.h>

// SCE loss: softmax over C=128, signed per-(class,bin) histogram of
// p - onehot, then sum |.| / (B*C).
// Round 10: label handling stripped from the hot path. Provisional
// "-1 into bin0 of label" as a single match-predicated shared atomic
// (right 99.6% of the time); bin-1 labels fixed in a rare guarded branch
// (mux only there); >2/15 labels fixed in the existing slow path.
// Otherwise R9: two register bins, coalesced split layout, running
// pointers, fused last-block finalize.

namespace {
constexpr int kC       = 128;
constexpr int kBins    = 15;
constexpr int kSegs    = kC * kBins;   // 1920
constexpr int kBlocks  = 888;          // 6 blocks/SM x 148 SMs
constexpr int kThreads = 256;
}

__device__ float    g_seg[kSegs];   // zero at load; last block re-zeroes
__device__ unsigned g_count;        // zero at load; last block re-zeroes

__global__ void __launch_bounds__(kThreads, 6)
sce_kernel(const float* __restrict__ logits, const int* __restrict__ labels,
           int B, float* __restrict__ out, float scale)
{
    __shared__ float s[kSegs];
    for (int i = threadIdx.x; i < kSegs; i += blockDim.x) s[i] = 0.0f;
    __syncthreads();

    const int lane = threadIdx.x & 31;
    const int wpb  = blockDim.x >> 5;
    const int gw   = blockIdx.x * wpb + (threadIdx.x >> 5);
    const int nw   = gridDim.x * wpb;
    const int h    = lane >> 4;          // which row of the pair
    const int L    = lane & 15;
    const int c0   = L << 2;             // classes c0..c0+3 and 64+c0..64+c0+3

    float bin0[8] = {0,0,0,0,0,0,0,0};   // p <= 1/15
    float bin1[8] = {0,0,0,0,0,0,0,0};   // 1/15 < p <= 2/15 (+ provisional)

    int row0 = gw * 2;
    const float* rp = logits + (size_t)(row0 + h) * kC + c0;
    const int*   lp = labels + row0 + h;
    const size_t rstep = (size_t)nw * 2 * kC;
    const int    lstep = nw * 2;

    for (; row0 + 1 < B; row0 += lstep, rp += rstep, lp += lstep) {
        const int lab = __ldg(lp);
        const float4 va = __ldg(reinterpret_cast<const float4*>(rp));
        const float4 vb = __ldg(reinterpret_cast<const float4*>(rp + 64));

        float e[8];
        e[0] = __expf(va.x); e[1] = __expf(va.y);
        e[2] = __expf(va.z); e[3] = __expf(va.w);
        e[4] = __expf(vb.x); e[5] = __expf(vb.y);
        e[6] = __expf(vb.z); e[7] = __expf(vb.w);

        float sm = ((e[0] + e[1]) + (e[2] + e[3]))
                 + ((e[4] + e[5]) + (e[6] + e[7]));
        #pragma unroll
        for (int o = 8; o > 0; o >>= 1)
            sm += __shfl_xor_sync(0xffffffffu, sm, o);

        const float inv = __fdividef(1.0f, sm);
        const float t1  = sm * (1.0f / 15.0f);   // e > t1 <=> p > 1/15
        const float t2  = sm * (2.0f / 15.0f);   // e > t2 <=> p > 2/15

        // branchless two-register binning
        #pragma unroll
        for (int j = 0; j < 8; j++) {
            if (e[j] > t1) bin1[j] = fmaf(e[j], inv, bin1[j]);
            else           bin0[j] = fmaf(e[j], inv, bin0[j]);
        }

        // label -1 provisionally into bin0 of lab (no mux; right 99.6%)
        const bool match = (L == ((lab & 63) >> 2));
        if (match) atomicAdd(&s[lab * kBins], -1.0f);

        const float m01 = fmaxf(fmaxf(e[0], e[1]), fmaxf(e[2], e[3]));
        const float m23 = fmaxf(fmaxf(e[4], e[5]), fmaxf(e[6], e[7]));
        const float mx  = fmaxf(m01, m23);

        // middle fix: label element in bin 1 (rare; mux only here)
        if (match && mx > t1) {
            const bool b0 = (lab & 1), b1 = (lab & 2), b2 = (lab & 64);
            const float m0 = b0 ? e[1] : e[0];
            const float m1 = b0 ? e[3] : e[2];
            const float m2 = b0 ? e[5] : e[4];
            const float m3 = b0 ? e[7] : e[6];
            const float n0 = b1 ? m1 : m0;
            const float n1 = b1 ? m3 : m2;
            const float esel = b2 ? n1 : n0;
            if (esel > t1 && esel <= t2) {
                atomicAdd(&s[lab * kBins + 0],  1.0f);  // cancel provisional
                atomicAdd(&s[lab * kBins + 1], -1.0f);  // -1 lives in bin 1
            }
        }

        if (mx > t2) {                       // rare (~10% of warp-iters)
            const int jlab = ((lab >> 6) << 2) | (lab & 3);
            #pragma unroll
            for (int j = 0; j < 8; j++) {
                if (e[j] > t2) {
                    const float p = e[j] * inv;
                    int k = __float2int_ru(p * 15.0f) - 1;   // >= 2 here
                    k = min(k, kBins - 1);
                    const bool isl = match && (j == jlab);
                    float add = p;
                    if (isl) {
                        add = p - 1.0f;                   // -1 moves with it
                        atomicAdd(&s[lab * kBins], 1.0f); // cancel provisional
                    }
                    const int cls = (j < 4) ? (c0 + j) : (64 + c0 + j - 4);
                    atomicAdd(&s[cls * kBins + k], add);
                    bin1[j] -= p;            // was provisionally in bin1
                }
            }
        }
    }

    // odd-B tail: one row, h==0 half does the work (h==1 joins shuffles)
    if (row0 < B) {
        const float* trp = logits + (size_t)row0 * kC + c0;
        const int lab = __ldg(labels + row0);
        const float4 va = __ldg(reinterpret_cast<const float4*>(trp));
        const float4 vb = __ldg(reinterpret_cast<const float4*>(trp + 64));
        float e[8];
        e[0] = __expf(va.x); e[1] = __expf(va.y);
        e[2] = __expf(va.z); e[3] = __expf(va.w);
        e[4] = __expf(vb.x); e[5] = __expf(vb.y);
        e[6] = __expf(vb.z); e[7] = __expf(vb.w);
        float sm = 0.0f;
        #pragma unroll
        for (int j = 0; j < 8; j++) sm += e[j];
        #pragma unroll
        for (int o = 8; o > 0; o >>= 1)
            sm += __shfl_xor_sync(0xffffffffu, sm, o);
        if (h == 0) {
            const float inv = __fdividef(1.0f, sm);
            const bool match = (L == ((lab & 63) >> 2));
            const int  jlab  = ((lab >> 6) << 2) | (lab & 3);
            #pragma unroll
            for (int j = 0; j < 8; j++) {
                const float p = e[j] * inv;
                int k = __float2int_ru(p * 15.0f) - 1;
                k = max(min(k, kBins - 1), 0);
                const bool isl = match && (j == jlab);
                const float add = isl ? (p - 1.0f) : p;
                const int cls = (j < 4) ? (c0 + j) : (64 + c0 + j - 4);
                atomicAdd(&s[cls * kBins + k], add);
            }
        }
    }

    // flush register accumulators into the block histogram
    #pragma unroll
    for (int j = 0; j < 8; j++) {
        const int cls = (j < 4) ? (c0 + j) : (64 + c0 + j - 4);
        atomicAdd(&s[cls * kBins + 0], bin0[j]);
        atomicAdd(&s[cls * kBins + 1], bin1[j]);
    }
    __syncthreads();

    // block histogram -> global
    for (int i = threadIdx.x; i < kSegs; i += blockDim.x) {
        const float v = s[i];
        if (v != 0.0f) atomicAdd(&g_seg[i], v);
    }

    // last-block finalize
    __shared__ bool isLast;
    __threadfence();
    if (threadIdx.x == 0)
        isLast = (atomicAdd(&g_count, 1u) == (unsigned)gridDim.x - 1u);
    __syncthreads();
    if (!isLast) return;

    __shared__ float red[32];
    float acc = 0.0f;
    for (int i = threadIdx.x; i < kSegs; i += blockDim.x) {
        acc += fabsf(__ldcg(&g_seg[i]));
        g_seg[i] = 0.0f;                   // reset for next replay
    }
    #pragma unroll
    for (int o = 16; o > 0; o >>= 1)
        acc += __shfl_xor_sync(0xffffffffu, acc, o);
    const int w = threadIdx.x >> 5;
    if (lane == 0) red[w] = acc;
    __syncthreads();
    if (w == 0) {
        const int nwarps = blockDim.x >> 5;
        acc = (lane < nwarps) ? red[lane] : 0.0f;
        #pragma unroll
        for (int o = 16; o > 0; o >>= 1)
            acc += __shfl_xor_sync(0xffffffffu, acc, o);
        if (threadIdx.x == 0) {
            out[0]  = acc * scale;
            g_count = 0u;                  // reset for next replay
        }
    }
}

extern "C" void kernel_launch(void* const* d_in, const int* in_sizes, int n_in,
                              void* d_out, int out_size) {
    const float* logits = (const float*)d_in[0];
    const int*   labels = (const int*)d_in[1];
    const int B = in_sizes[1];
    const float scale = 1.0f / ((float)B * (float)kC);
    sce_kernel<<<kBlocks, kThreads>>>(logits, labels, B, (float*)d_out, scale);
}